// round 2
// baseline (speedup 1.0000x reference)
#include <cuda_runtime.h>
#include <cuda_bf16.h>

// Fully fused persistent kernel.
//   r_i   = rowsum(x_i)
//   s_g   = relu(Gamma * mean_g)   (empty seg -> relu(Gamma * r_0))
//   out[i][:] = relu(Lambda * (r_i + 128*s_{sub[i]}))
// Traffic: read x 128MB + write out 128MB. Grid barrier via last-block pattern;
// all 1024 blocks co-resident (148 SMs * 8 blocks >= 1024) so spin is safe.

#define NROWS 131072
#define DIN 256
#define NSUB 64
#define ROWS_PER_BLOCK 128
#define BLOCK_THREADS 256
#define GRID_BLOCKS (NROWS / ROWS_PER_BLOCK)  // 1024

__device__ float g_segsum[NSUB];   // zero-initialized; reset by last block each run
__device__ float g_segcnt[NSUB];
__device__ float g_stab[NSUB];
__device__ float g_row0sum;
__device__ int   g_c1;             // phase-1 arrival counter
__device__ int   g_c2;             // phase-2 departure counter
__device__ volatile int g_flag;    // table-ready flag

__global__ __launch_bounds__(BLOCK_THREADS, 8) void fused_kernel(
    const float* __restrict__ x,
    const int*   __restrict__ sub,
    const float* __restrict__ Gamma,
    const float* __restrict__ Lambda,
    float*       __restrict__ out)
{
    __shared__ float ssum[NSUB];
    __shared__ float scnt[NSUB];
    __shared__ float srow[ROWS_PER_BLOCK];
    __shared__ float stab[NSUB];

    const int t    = threadIdx.x;
    const int warp = t >> 5;
    const int lane = t & 31;
    const int row0 = blockIdx.x * ROWS_PER_BLOCK;

    if (t < NSUB) { ssum[t] = 0.f; scnt[t] = 0.f; }
    __syncthreads();

    // ---- Phase 1: rowsums + segment partials ----
    #pragma unroll 1
    for (int r = warp; r < ROWS_PER_BLOCK; r += (BLOCK_THREADS >> 5)) {
        const int row = row0 + r;
        const float4* p = reinterpret_cast<const float4*>(x + (size_t)row * DIN);
        float4 a = __ldcs(p + lane);
        float4 b = __ldcs(p + lane + 32);
        float s = (a.x + a.y) + (a.z + a.w) + (b.x + b.y) + (b.z + b.w);
        #pragma unroll
        for (int o = 16; o; o >>= 1) s += __shfl_xor_sync(0xffffffffu, s, o);
        if (lane == 0) {
            srow[r] = s;
            if (row == 0) g_row0sum = s;      // done by thread 0 (warp 0, lane 0)
            const int sg = __ldg(sub + row);
            atomicAdd(&ssum[sg], s);
            atomicAdd(&scnt[sg], 1.f);
        }
    }
    __syncthreads();

    // block partials -> global accumulators
    if (t < NSUB && scnt[t] != 0.f) {
        atomicAdd(&g_segsum[t], ssum[t]);
        atomicAdd(&g_segcnt[t], scnt[t]);
        __threadfence();
    }
    __syncthreads();

    // ---- Grid barrier: last block builds the table ----
    if (t == 0) {
        __threadfence();
        const int ticket = atomicAdd(&g_c1, 1);
        if (ticket == GRID_BLOCKS - 1) {
            const float gam = Gamma[0];
            const float r0  = g_row0sum;
            #pragma unroll 1
            for (int i = 0; i < NSUB; i++) {
                const float cnt = g_segsum[i] * 0.f + g_segcnt[i];   // force reads
                const float sm  = g_segsum[i];
                const float m   = (cnt > 0.f) ? (sm / cnt) : r0;
                const float sv  = gam * m;
                g_stab[i] = sv > 0.f ? sv : 0.f;
                g_segsum[i] = 0.f;            // reset for next graph replay
                g_segcnt[i] = 0.f;
            }
            __threadfence();
            g_flag = 1;
        }
        while (g_flag == 0) { }               // all blocks resident -> safe spin
    }
    __syncthreads();

    if (t < NSUB) stab[t] = g_stab[t];
    __syncthreads();

    // ---- Phase 2: broadcast-write output ----
    const float lam = Lambda[0];
    #pragma unroll 1
    for (int r = warp; r < ROWS_PER_BLOCK; r += (BLOCK_THREADS >> 5)) {
        const int row = row0 + r;
        float o = lam * (srow[r] + 128.f * stab[__ldg(sub + row)]);
        o = o > 0.f ? o : 0.f;
        const float4 v = make_float4(o, o, o, o);
        float4* p = reinterpret_cast<float4*>(out + (size_t)row * DIN);
        __stcs(p + lane, v);
        __stcs(p + lane + 32, v);
    }

    // ---- Epilogue: last block resets barrier state for next replay ----
    __syncthreads();
    if (t == 0) {
        __threadfence();
        const int ticket = atomicAdd(&g_c2, 1);
        if (ticket == GRID_BLOCKS - 1) {
            g_c1 = 0;
            g_c2 = 0;
            g_flag = 0;
        }
    }
}

extern "C" void kernel_launch(void* const* d_in, const int* in_sizes, int n_in,
                              void* d_out, int out_size)
{
    const float* x      = (const float*)d_in[0];
    const int*   sub    = (const int*)d_in[1];
    const float* Gamma  = (const float*)d_in[2];
    const float* Lambda = (const float*)d_in[3];
    float* out = (float*)d_out;

    fused_kernel<<<GRID_BLOCKS, BLOCK_THREADS>>>(x, sub, Gamma, Lambda, out);
}

// round 4
// speedup vs baseline: 1.1475x; 1.1475x over previous
#include <cuda_runtime.h>
#include <cuda_bf16.h>

// 2-kernel version, no grid barrier, no zero kernel.
//   pass1: rowsums (unroll-4, MLP=8) + segment sums via smem -> global atomics
//   pass2: builds 64-entry table per block, streams output; last-arriving
//          block resets accumulators for the next graph replay (ticket, no wait).

#define NROWS 131072
#define DIN   256
#define NSUB  64
#define RPB   128          // rows per block
#define BT    256          // threads per block (8 warps, 16 rows/warp)
#define GRID  (NROWS / RPB)

__device__ float g_rowsum[NROWS];
__device__ float g_segsum[NSUB];   // zero-init; reset by pass2's last block
__device__ float g_segcnt[NSUB];
__device__ int   g_ticket;

__global__ __launch_bounds__(BT) void pass1_kernel(
    const float* __restrict__ x, const int* __restrict__ sub)
{
    __shared__ float ssum[NSUB];
    __shared__ float scnt[NSUB];
    const int t = threadIdx.x, warp = t >> 5, lane = t & 31;
    if (t < NSUB) { ssum[t] = 0.f; scnt[t] = 0.f; }
    __syncthreads();

    const int rowbase = blockIdx.x * RPB + warp * 16;

    #pragma unroll 1
    for (int j = 0; j < 16; j += 4) {
        float s0, s1, s2, s3;
        {
            const float4* p0 = reinterpret_cast<const float4*>(x + (size_t)(rowbase + j + 0) * DIN);
            const float4* p1 = reinterpret_cast<const float4*>(x + (size_t)(rowbase + j + 1) * DIN);
            const float4* p2 = reinterpret_cast<const float4*>(x + (size_t)(rowbase + j + 2) * DIN);
            const float4* p3 = reinterpret_cast<const float4*>(x + (size_t)(rowbase + j + 3) * DIN);
            float4 a0 = __ldcs(p0 + lane), b0 = __ldcs(p0 + lane + 32);
            float4 a1 = __ldcs(p1 + lane), b1 = __ldcs(p1 + lane + 32);
            float4 a2 = __ldcs(p2 + lane), b2 = __ldcs(p2 + lane + 32);
            float4 a3 = __ldcs(p3 + lane), b3 = __ldcs(p3 + lane + 32);
            s0 = (a0.x + a0.y) + (a0.z + a0.w) + (b0.x + b0.y) + (b0.z + b0.w);
            s1 = (a1.x + a1.y) + (a1.z + a1.w) + (b1.x + b1.y) + (b1.z + b1.w);
            s2 = (a2.x + a2.y) + (a2.z + a2.w) + (b2.x + b2.y) + (b2.z + b2.w);
            s3 = (a3.x + a3.y) + (a3.z + a3.w) + (b3.x + b3.y) + (b3.z + b3.w);
        }
        #pragma unroll
        for (int o = 16; o; o >>= 1) {
            s0 += __shfl_xor_sync(0xffffffffu, s0, o);
            s1 += __shfl_xor_sync(0xffffffffu, s1, o);
            s2 += __shfl_xor_sync(0xffffffffu, s2, o);
            s3 += __shfl_xor_sync(0xffffffffu, s3, o);
        }
        // lanes 0..3 each commit one row (spread atomics)
        if (lane < 4) {
            const float sv = (lane == 0) ? s0 : (lane == 1) ? s1 : (lane == 2) ? s2 : s3;
            const int row = rowbase + j + lane;
            g_rowsum[row] = sv;
            const int sg = __ldg(sub + row);
            atomicAdd(&ssum[sg], sv);
            atomicAdd(&scnt[sg], 1.f);
        }
    }
    __syncthreads();

    if (t < NSUB && scnt[t] != 0.f) {
        atomicAdd(&g_segsum[t], ssum[t]);
        atomicAdd(&g_segcnt[t], scnt[t]);
    }
}

__global__ __launch_bounds__(BT) void pass2_kernel(
    const int*   __restrict__ sub,
    const float* __restrict__ Gamma,
    const float* __restrict__ Lambda,
    float*       __restrict__ out)
{
    __shared__ float stab[NSUB];   // holds 128 * relu(Gamma * mean_g)
    const int t = threadIdx.x, warp = t >> 5, lane = t & 31;

    if (t < NSUB) {
        const float cnt = g_segcnt[t];
        const float m   = (cnt > 0.f) ? (g_segsum[t] / cnt) : g_rowsum[0];
        const float sv  = Gamma[0] * m;
        stab[t] = (sv > 0.f) ? 128.f * sv : 0.f;
    }
    __syncthreads();

    // Ticket: last block to get here resets accumulators for the next replay.
    // Nobody waits on anything.
    if (t == 0) {
        __threadfence();
        const int tk = atomicAdd(&g_ticket, 1);
        if (tk == GRID - 1) {
            #pragma unroll
            for (int i = 0; i < NSUB; i++) { g_segsum[i] = 0.f; g_segcnt[i] = 0.f; }
            __threadfence();
            g_ticket = 0;
        }
    }

    const float lam = Lambda[0];
    const int rowbase = blockIdx.x * RPB + warp * 16;

    #pragma unroll 1
    for (int j = 0; j < 16; j += 4) {
        #pragma unroll
        for (int u = 0; u < 4; u++) {
            const int row = rowbase + j + u;
            float o = lam * (g_rowsum[row] + stab[__ldg(sub + row)]);
            o = (o > 0.f) ? o : 0.f;
            const float4 v = make_float4(o, o, o, o);
            float4* p = reinterpret_cast<float4*>(out + (size_t)row * DIN);
            __stcs(p + lane, v);
            __stcs(p + lane + 32, v);
        }
    }
}

extern "C" void kernel_launch(void* const* d_in, const int* in_sizes, int n_in,
                              void* d_out, int out_size)
{
    const float* x      = (const float*)d_in[0];
    const int*   sub    = (const int*)d_in[1];
    const float* Gamma  = (const float*)d_in[2];
    const float* Lambda = (const float*)d_in[3];
    float* out = (float*)d_out;

    pass1_kernel<<<GRID, BT>>>(x, sub);
    pass2_kernel<<<GRID, BT>>>(sub, Gamma, Lambda, out);
}